// round 2
// baseline (speedup 1.0000x reference)
#include <cuda_runtime.h>
#include <cstddef>

#define FULL_MASK 0xFFFFFFFFu

// Fast, accurate-enough sigmoid: ex2.approx (via __expf) + rcp.approx.
// Both have ~1e-7 relative error; far inside the 1e-3 budget.
__device__ __forceinline__ float sigmoid_fast(float x) {
    float e = __expf(-x);
    float d = 1.0f + e;
    float r;
    asm("rcp.approx.f32 %0, %1;" : "=f"(r) : "f"(d));
    return r;
}

// One warp per batch element. lane = u + 16*half.
//   u    = hidden unit index (0..15)
//   half = which 8 of the 16 k-terms of the recurrent dot this lane accumulates.
// Partial sums combined with shfl_xor(16); gates computed redundantly on both
// halves (keeps h replicated, avoids a second exchange); only half==0 stores.
__global__ __launch_bounds__(128)
void gru_decoder_kernel(const float* __restrict__ enc,      // [1024,16]
                        const int*   __restrict__ targets,  // [1024,2048]
                        const float* __restrict__ emb,      // [4,16]
                        const float* __restrict__ kernel,   // [16,48]
                        const float* __restrict__ reck,     // [16,48]
                        const float* __restrict__ bias,     // [2,48]
                        float* __restrict__ out)            // [1024,2048,16]
{
    constexpr int T = 2048;
    constexpr int U = 16;

    // Precomputed input projection table, one row per vocab id v (V=4):
    //   tab[v*48 + j] = (emb[v] @ kernel)[j] + bias0[j] + (j<32 ? bias1[j] : 0)
    // (bias1 for the z/r gates adds linearly pre-sigmoid, so it folds in;
    //  bias1 for the h-gate is multiplied by r, so it stays separate as brh.)
    __shared__ float tab[4 * 48];

    const int tid = threadIdx.x;
    // NOTE: block has 128 threads but the table has 192 entries — stride it.
    for (int idx = tid; idx < 192; idx += 128) {
        const int v = idx / 48;
        const int j = idx % 48;
        float s = bias[j] + (j < 32 ? bias[48 + j] : 0.0f);
        #pragma unroll
        for (int e = 0; e < 16; ++e)
            s = fmaf(emb[v * 16 + e], kernel[e * 48 + j], s);
        tab[idx] = s;
    }
    __syncthreads();

    const int lane  = tid & 31;
    const int warp  = tid >> 5;
    const int b     = blockIdx.x * 4 + warp;   // 256 blocks * 4 warps = 1024
    const int u     = lane & 15;
    const int kbase = (lane >> 4) * 8;         // this lane's k-range start

    // Recurrent weight slices for my (u, k-range): 24 registers.
    float wz[8], wr[8], wh[8];
    #pragma unroll
    for (int i = 0; i < 8; ++i) {
        const int k = kbase + i;
        wz[i] = reck[k * 48 + u];
        wr[i] = reck[k * 48 + 16 + u];
        wh[i] = reck[k * 48 + 32 + u];
    }
    const float brh = bias[48 + 32 + u];  // recurrent bias, h-gate (inside r*)

    float h = enc[b * U + u];             // replicated across both halves

    const int* pt = targets + (size_t)b * T;
    float* po = out + ((size_t)b * T) * U + u;

    int tv = pt[lane];                    // 32 targets buffered per warp
    for (int t0 = 0; t0 < T; t0 += 32) {
        // prefetch next target block while this one is consumed
        const int tvn = (t0 + 32 < T) ? pt[t0 + 32 + lane] : 0;

        #pragma unroll 8
        for (int s = 0; s < 32; ++s) {
            const int v  = __shfl_sync(FULL_MASK, tv, s);
            const int tb = v * 48 + u;
            const float xz = tab[tb];         // includes b0_z + b1_z
            const float xr = tab[tb + 16];    // includes b0_r + b1_r
            const float xh = tab[tb + 32];    // includes b0_h only

            // broadcast the 8 h-values this half needs
            float hk[8];
            #pragma unroll
            for (int i = 0; i < 8; ++i)
                hk[i] = __shfl_sync(FULL_MASK, h, kbase + i);

            // partial dots, 2 independent chains per gate for ILP
            float az0 = 0.f, az1 = 0.f, ar0 = 0.f, ar1 = 0.f, ah0 = 0.f, ah1 = 0.f;
            #pragma unroll
            for (int i = 0; i < 8; i += 2) {
                az0 = fmaf(hk[i],     wz[i],     az0);
                az1 = fmaf(hk[i + 1], wz[i + 1], az1);
                ar0 = fmaf(hk[i],     wr[i],     ar0);
                ar1 = fmaf(hk[i + 1], wr[i + 1], ar1);
                ah0 = fmaf(hk[i],     wh[i],     ah0);
                ah1 = fmaf(hk[i + 1], wh[i + 1], ah1);
            }
            float fz = az0 + az1;
            float fr = ar0 + ar1;
            float fh = ah0 + ah1;
            // combine the two K-halves
            fz += __shfl_xor_sync(FULL_MASK, fz, 16);
            fr += __shfl_xor_sync(FULL_MASK, fr, 16);
            fh += __shfl_xor_sync(FULL_MASK, fh, 16);

            const float z = sigmoid_fast(xz + fz);
            const float r = sigmoid_fast(xr + fr);
            const float c = sigmoid_fast(fmaf(r, fh + brh, xh));  // sigmoid cand!
            h = c + z * (h - c);   // == z*h + (1-z)*c

            if (lane < 16) po[(t0 + s) * U] = h;   // coalesced 64B per batch
        }
        tv = tvn;
    }
}

extern "C" void kernel_launch(void* const* d_in, const int* in_sizes, int n_in,
                              void* d_out, int out_size) {
    (void)in_sizes; (void)n_in; (void)out_size;
    const float* enc     = (const float*)d_in[0];
    const int*   targets = (const int*)  d_in[1];
    const float* emb     = (const float*)d_in[2];
    const float* kernel  = (const float*)d_in[3];
    const float* reck    = (const float*)d_in[4];
    const float* bias    = (const float*)d_in[5];
    float* out = (float*)d_out;

    gru_decoder_kernel<<<256, 128>>>(enc, targets, emb, kernel, reck, bias, out);
}

// round 3
// speedup vs baseline: 1.3100x; 1.3100x over previous
#include <cuda_runtime.h>
#include <cstddef>

#define FULL_MASK 0xFFFFFFFFu

// Exact-ish sigmoid: ex2.approx + rcp.approx (~1e-7 rel err).
// Used only for z, which is OFF the critical path.
__device__ __forceinline__ float sigmoid_exact(float x) {
    float e = __expf(-x);
    float d = 1.0f + e;
    float r;
    asm("rcp.approx.f32 %0, %1;" : "=f"(r) : "f"(d));
    return r;
}

// Half-argument tanh-based sigmoid: caller provides x/2 (folded into weights).
// sigmoid(x) = 0.5*tanh(x/2) + 0.5  -> one MUFU.TANH + one FFMA.
__device__ __forceinline__ float sigmoid_from_half(float xh) {
    float t;
    asm("tanh.approx.f32 %0, %1;" : "=f"(t) : "f"(xh));
    return fmaf(0.5f, t, 0.5f);
}

// One warp per batch element. lane = u + 16*half.
//   u    = hidden unit index (0..15)
//   half = which 8 of the 16 k-terms of the recurrent dot this lane accumulates.
// Partial sums combined with shfl_xor(16); gates computed redundantly on both
// halves; only half==0 stores.
__global__ __launch_bounds__(128)
void gru_decoder_kernel(const float* __restrict__ enc,      // [1024,16]
                        const int*   __restrict__ targets,  // [1024,2048]
                        const float* __restrict__ emb,      // [4,16]
                        const float* __restrict__ kernel,   // [16,48]
                        const float* __restrict__ reck,     // [16,48]
                        const float* __restrict__ bias,     // [2,48]
                        float* __restrict__ out)            // [1024,2048,16]
{
    constexpr int T = 2048;
    constexpr int U = 16;

    // Precomputed input projection table, one row per vocab id v (V=4):
    //   j <  16 (z): full scale,   (emb@kernel)[j] + b0[j] + b1[j]
    //   16<=j<32 (r): HALF scale, ((emb@kernel)[j] + b0[j] + b1[j]) * 0.5
    //   32<=j<48 (h): HALF scale, ((emb@kernel)[j] + b0[j]) * 0.5
    // The 0.5 folds sigmoid(x)=0.5*tanh(x/2)+0.5 into the projections.
    __shared__ float tab[4 * 48];

    const int tid = threadIdx.x;
    for (int idx = tid; idx < 192; idx += 128) {
        const int v = idx / 48;
        const int j = idx % 48;
        float s = bias[j] + (j < 32 ? bias[48 + j] : 0.0f);
        #pragma unroll
        for (int e = 0; e < 16; ++e)
            s = fmaf(emb[v * 16 + e], kernel[e * 48 + j], s);
        tab[idx] = (j < 16) ? s : 0.5f * s;
    }
    __syncthreads();

    const int lane  = tid & 31;
    const int warp  = tid >> 5;
    const int b     = blockIdx.x * 4 + warp;   // 256 blocks * 4 warps = 1024
    const int u     = lane & 15;
    const int kbase = (lane >> 4) * 8;         // this lane's k-range start

    // Recurrent weight slices. wr/wh pre-halved for the tanh form.
    float wz[8], wr[8], wh[8];
    #pragma unroll
    for (int i = 0; i < 8; ++i) {
        const int k = kbase + i;
        wz[i] = reck[k * 48 + u];
        wr[i] = 0.5f * reck[k * 48 + 16 + u];
        wh[i] = 0.5f * reck[k * 48 + 32 + u];
    }
    const float brh = 0.5f * bias[48 + 32 + u];  // recurrent h-bias, halved

    float h = enc[b * U + u];             // replicated across both halves

    const int* pt = targets + (size_t)b * T;
    float* po = out + ((size_t)b * T) * U + u;

    int tv = pt[lane];                    // 32 targets buffered per warp
    for (int t0 = 0; t0 < T; t0 += 32) {
        const int tvn = (t0 + 32 < T) ? pt[t0 + 32 + lane] : 0;

        #pragma unroll 8
        for (int s = 0; s < 32; ++s) {
            const int v  = __shfl_sync(FULL_MASK, tv, s);
            const int tb = v * 48 + u;
            const float xz = tab[tb];         // full scale
            const float xr = tab[tb + 16];    // half scale
            const float xh = tab[tb + 32];    // half scale

            // broadcast the 8 h-values this half needs
            float hk[8];
            #pragma unroll
            for (int i = 0; i < 8; ++i)
                hk[i] = __shfl_sync(FULL_MASK, h, kbase + i);

            // partial dots, 2 independent chains per gate for ILP
            float az0 = 0.f, az1 = 0.f, ar0 = 0.f, ar1 = 0.f, ah0 = 0.f, ah1 = 0.f;
            #pragma unroll
            for (int i = 0; i < 8; i += 2) {
                az0 = fmaf(hk[i],     wz[i],     az0);
                az1 = fmaf(hk[i + 1], wz[i + 1], az1);
                ar0 = fmaf(hk[i],     wr[i],     ar0);
                ar1 = fmaf(hk[i + 1], wr[i + 1], ar1);
                ah0 = fmaf(hk[i],     wh[i],     ah0);
                ah1 = fmaf(hk[i + 1], wh[i + 1], ah1);
            }
            float fz = az0 + az1;
            float fr = ar0 + ar1;   // half scale
            float fh = ah0 + ah1;   // half scale
            fz += __shfl_xor_sync(FULL_MASK, fz, 16);
            fr += __shfl_xor_sync(FULL_MASK, fr, 16);
            fh += __shfl_xor_sync(FULL_MASK, fh, 16);

            // r and c via tanh (on the serial chain); z exact (off the chain)
            const float r = sigmoid_from_half(xr + fr);
            const float c = sigmoid_from_half(fmaf(r, fh + brh, xh));
            const float z = sigmoid_exact(xz + fz);
            h = c + z * (h - c);   // == z*h + (1-z)*c

            if (lane < 16) po[(t0 + s) * U] = h;   // coalesced 64B per batch
        }
        tv = tvn;
    }
}

extern "C" void kernel_launch(void* const* d_in, const int* in_sizes, int n_in,
                              void* d_out, int out_size) {
    (void)in_sizes; (void)n_in; (void)out_size;
    const float* enc     = (const float*)d_in[0];
    const int*   targets = (const int*)  d_in[1];
    const float* emb     = (const float*)d_in[2];
    const float* kernel  = (const float*)d_in[3];
    const float* reck    = (const float*)d_in[4];
    const float* bias    = (const float*)d_in[5];
    float* out = (float*)d_out;

    gru_decoder_kernel<<<256, 128>>>(enc, targets, emb, kernel, reck, bias, out);
}